// round 7
// baseline (speedup 1.0000x reference)
#include <cuda_runtime.h>
#include <cuda_fp16.h>
#include <stdint.h>

#define BB 2
#define TT 4096
#define CC 128
#define HH 8
#define DD 16
#define NROWS (BB*TT)   // 8192
#define QTILES (TT/128) // 32
#define KSTR 24         // attn smem row stride in halfs (48B) -> conflict-free ldmatrix
#define PSTR 136        // projection smem row stride in halfs (272B) -> conflict-free ldmatrix

// f16 scratch
__device__ __half g_qh[BB*HH*TT*DD];     // q (pre-scaled by 0.25*log2e)
__device__ __half g_kh[BB*HH*TT*DD];
__device__ __half g_vh[BB*HH*TT*DD];
__device__ __half g_attnh[NROWS*CC];     // attention output f16

// ---------------- helpers ----------------
__device__ __forceinline__ uint32_t smem_u32(const void* p) {
    uint32_t a; asm("{ .reg .u64 t; cvta.to.shared.u64 t, %1; cvt.u32.u64 %0, t; }" : "=r"(a) : "l"(p));
    return a;
}
__device__ __forceinline__ uint32_t packh2(float lo, float hi) {
    uint32_t d; asm("cvt.rn.f16x2.f32 %0, %1, %2;" : "=r"(d) : "f"(hi), "f"(lo)); return d;
}
__device__ __forceinline__ uint32_t h2ex2(uint32_t x) {
    uint32_t r; asm("ex2.approx.f16x2 %0, %1;" : "=r"(r) : "r"(x)); return r;
}
__device__ __forceinline__ uint32_t hadd2u(uint32_t a, uint32_t b) {
    uint32_t r; asm("add.f16x2 %0, %1, %2;" : "=r"(r) : "r"(a), "r"(b)); return r;
}
__device__ __forceinline__ float2 h2f2(uint32_t v) {
    __half2 h = *(__half2*)&v;
    return __half22float2(h);
}
__device__ __forceinline__ void ldsm_x4(uint32_t addr, uint32_t& r0, uint32_t& r1,
                                        uint32_t& r2, uint32_t& r3) {
    asm volatile("ldmatrix.sync.aligned.m8n8.x4.shared.b16 {%0,%1,%2,%3}, [%4];"
                 : "=r"(r0), "=r"(r1), "=r"(r2), "=r"(r3) : "r"(addr));
}
__device__ __forceinline__ void ldsm_x4_t(uint32_t addr, uint32_t& r0, uint32_t& r1,
                                          uint32_t& r2, uint32_t& r3) {
    asm volatile("ldmatrix.sync.aligned.m8n8.x4.trans.shared.b16 {%0,%1,%2,%3}, [%4];"
                 : "=r"(r0), "=r"(r1), "=r"(r2), "=r"(r3) : "r"(addr));
}
__device__ __forceinline__ void hmma(float* d, const uint32_t* a, const uint32_t* b, const float* c) {
    asm volatile(
        "mma.sync.aligned.m16n8k16.row.col.f32.f16.f16.f32 "
        "{%0,%1,%2,%3}, {%4,%5,%6,%7}, {%8,%9}, {%10,%11,%12,%13};"
        : "=f"(d[0]), "=f"(d[1]), "=f"(d[2]), "=f"(d[3])
        : "r"(a[0]), "r"(a[1]), "r"(a[2]), "r"(a[3]),
          "r"(b[0]), "r"(b[1]),
          "f"(c[0]), "f"(c[1]), "f"(c[2]), "f"(c[3]));
}
__device__ __forceinline__ void cpa16(uint32_t dst, const void* src) {
    asm volatile("cp.async.cg.shared.global [%0], [%1], 16;" :: "r"(dst), "l"(src));
}
#define CP_COMMIT() asm volatile("cp.async.commit_group;" ::: "memory")
#define CP_WAIT0()  asm volatile("cp.async.wait_group 0;" ::: "memory")

// ---------------------------------------------------------------------------
// Kernel 1: QKV projection via HMMA, smem-staged.  grid=(256,3), block=128.
// Writes f16 scattered to [B,H,T,D]; q pre-scaled by 0.25*log2(e).
// ---------------------------------------------------------------------------
__global__ void __launch_bounds__(128) qkv_hmma_kernel(const float* __restrict__ x,
                                                       const float* __restrict__ Wk,
                                                       const float* __restrict__ Wq,
                                                       const float* __restrict__ Wv)
{
    const int sel = blockIdx.y;                 // 0=q 1=k 2=v
    const float* W = (sel == 0) ? Wq : (sel == 1) ? Wk : Wv;
    __half* dstH = (sel == 0) ? g_qh : (sel == 1) ? g_kh : g_vh;
    const float osc = (sel == 0) ? (0.25f * 1.44269504f) : 1.0f;

    __shared__ __align__(16) __half xs[32 * PSTR];
    __shared__ __align__(16) __half ws[128 * PSTR];
    const uint32_t xs_sm = smem_u32(xs);
    const uint32_t ws_sm = smem_u32(ws);

    const int m0 = blockIdx.x * 32;
    const int tid = threadIdx.x;
    const int lane = tid & 31;
    const int w = tid >> 5;
    const int n0 = w * 32;
    const int gr = lane >> 2, tig = lane & 3;
    const int lr = lane & 7,  mi = lane >> 3;

    {
        const float4* xsrc = (const float4*)(x + (size_t)m0 * CC);
#pragma unroll
        for (int i = tid; i < 32 * 32; i += 128) {
            const int row = i >> 5, c4 = i & 31;
            float4 v = xsrc[i];
            *(uint2*)(xs + row * PSTR + c4 * 4) =
                make_uint2(packh2(v.x, v.y), packh2(v.z, v.w));
        }
        const float4* wsrc = (const float4*)W;
#pragma unroll
        for (int i = tid; i < 128 * 32; i += 128) {
            const int row = i >> 5, c4 = i & 31;
            float4 v = wsrc[i];
            *(uint2*)(ws + row * PSTR + c4 * 4) =
                make_uint2(packh2(v.x, v.y), packh2(v.z, v.w));
        }
    }
    __syncthreads();

    float acc[2][4][4];
#pragma unroll
    for (int m = 0; m < 2; m++)
#pragma unroll
        for (int nt = 0; nt < 4; nt++)
#pragma unroll
            for (int i = 0; i < 4; i++) acc[m][nt][i] = 0.f;

#pragma unroll
    for (int ks = 0; ks < 8; ks++) {
        uint32_t a[2][4];
#pragma unroll
        for (int m = 0; m < 2; m++)
            ldsm_x4(xs_sm + ((m * 16 + (lane & 15)) * PSTR + ks * 16 + (lane >> 4) * 8) * 2,
                    a[m][0], a[m][1], a[m][2], a[m][3]);
        uint32_t kfb[4][2];
#pragma unroll
        for (int p = 0; p < 2; p++) {
            uint32_t r0, r1, r2, r3;
            ldsm_x4(ws_sm + ((n0 + p * 16 + ((mi & 2) ? 8 : 0) + lr) * PSTR
                             + ks * 16 + (mi & 1) * 8) * 2, r0, r1, r2, r3);
            kfb[2*p][0]   = r0; kfb[2*p][1]   = r1;
            kfb[2*p+1][0] = r2; kfb[2*p+1][1] = r3;
        }
#pragma unroll
        for (int nt = 0; nt < 4; nt++) {
            hmma(acc[0][nt], a[0], kfb[nt], acc[0][nt]);
            hmma(acc[1][nt], a[1], kfb[nt], acc[1][nt]);
        }
    }

    uint32_t* d32 = (uint32_t*)dstH;
#pragma unroll
    for (int m = 0; m < 2; m++) {
        const int row = m0 + m * 16 + gr;
        const int bb = row >> 12, t = row & (TT - 1);
#pragma unroll
        for (int nt = 0; nt < 4; nt++) {
            const int col = n0 + nt * 8 + 2 * tig;
            const int h = col >> 4, d = col & 15;
            const size_t idx = ((size_t)(bb * HH + h) * TT + t) * 8 + (d >> 1);
            d32[idx]      = packh2(acc[m][nt][0] * osc, acc[m][nt][1] * osc);
            d32[idx + 64] = packh2(acc[m][nt][2] * osc, acc[m][nt][3] * osc);
        }
    }
}

// ---------------------------------------------------------------------------
// Kernel 2: HMMA flash attention.  l via HADD2 (no ones-column HMMAs),
// single barrier per tile, cp.async double buffering.
// grid=(QTILES,HH,BB), block=128; warp owns 32 query rows.
// ---------------------------------------------------------------------------
__global__ void __launch_bounds__(128) attn_mma_kernel()
{
    const int qt  = (QTILES - 1) - blockIdx.x;   // heavy CTAs first
    const int h   = blockIdx.y;
    const int b   = blockIdx.z;
    const int tid = threadIdx.x;
    const int w   = tid >> 5;
    const int lane = tid & 31;
    const int gr  = lane >> 2;
    const int tig = lane & 3;
    const int lr  = lane & 7;
    const int mi  = lane >> 3;

    __shared__ __align__(16) __half Ks[2][128 * KSTR];
    __shared__ __align__(16) __half Vs[2][128 * KSTR];
    const uint32_t ksb = smem_u32(Ks);
    const uint32_t vsb = smem_u32(Vs);
    const uint32_t BUFB = 128 * KSTR * 2;

    const size_t head = (size_t)(b * HH + h) * TT;
    const __half* kh = g_kh + head * DD;
    const __half* vh = g_vh + head * DD;

    // Q A-fragments (pre-scaled, pre-packed f16)
    uint32_t qa[2][4];
    {
        const uint32_t* qh32 = (const uint32_t*)g_qh + (head + (size_t)qt * 128) * 8;
#pragma unroll
        for (int m = 0; m < 2; m++) {
            const int base = (w * 32 + m * 16 + gr) * 8 + tig;
            qa[m][0] = qh32[base];     qa[m][1] = qh32[base + 64];
            qa[m][2] = qh32[base + 4]; qa[m][3] = qh32[base + 68];
        }
    }

    float of[2][2][4];
#pragma unroll
    for (int m = 0; m < 2; m++)
#pragma unroll
        for (int n = 0; n < 2; n++)
#pragma unroll
            for (int i = 0; i < 4; i++) of[m][n][i] = 0.f;
    float lp[2][2] = {{0.f, 0.f}, {0.f, 0.f}};
    const float zc[4] = {0.f, 0.f, 0.f, 0.f};

    const int ntiles = qt + 1;
    const uint32_t krow_off = (uint32_t)tid * (KSTR * 2);

    // prefetch tile 0 into buffer 0
    {
        const __half* ksrc = kh + (size_t)tid * DD;
        const __half* vsrc = vh + (size_t)tid * DD;
        cpa16(ksb + krow_off,      ksrc);
        cpa16(ksb + krow_off + 16, ksrc + 8);
        cpa16(vsb + krow_off,      vsrc);
        cpa16(vsb + krow_off + 16, vsrc + 8);
        CP_COMMIT();
    }

    for (int kt = 0; kt < ntiles; kt++) {
        CP_WAIT0();
        __syncthreads();   // data visible to all warps; also guards buffer overwrite below

        if (kt + 1 < ntiles) {
            const uint32_t nb = ((kt + 1) & 1) * BUFB;
            const __half* ksrc = kh + (size_t)((kt + 1) * 128 + tid) * DD;
            const __half* vsrc = vh + (size_t)((kt + 1) * 128 + tid) * DD;
            cpa16(ksb + nb + krow_off,      ksrc);
            cpa16(ksb + nb + krow_off + 16, ksrc + 8);
            cpa16(vsb + nb + krow_off,      vsrc);
            cpa16(vsb + nb + krow_off + 16, vsrc + 8);
            CP_COMMIT();
        }

        const uint32_t ks_sm = ksb + (kt & 1) * BUFB;
        const uint32_t vs_sm = vsb + (kt & 1) * BUFB;
        const bool diag = (kt == qt);
        const int cmax = diag ? (w + 1) : 4;

        for (int c = 0; c < cmax; c++) {
            const int kstart = kt * 128 + c * 32;

            uint32_t kfb[4][2];
#pragma unroll
            for (int p = 0; p < 2; p++) {
                uint32_t krow = c * 32 + p * 16 + ((mi & 2) ? 8 : 0) + lr;
                uint32_t kcol = (mi & 1) * 8;
                uint32_t r0, r1, r2, r3;
                ldsm_x4(ks_sm + (krow * KSTR + kcol) * 2, r0, r1, r2, r3);
                kfb[2*p][0]   = r0; kfb[2*p][1]   = r1;
                kfb[2*p+1][0] = r2; kfb[2*p+1][1] = r3;
            }

            float sc[2][4][4];
#pragma unroll
            for (int m = 0; m < 2; m++)
#pragma unroll
                for (int nt = 0; nt < 4; nt++)
                    hmma(sc[m][nt], qa[m], kfb[nt], zc);

            const bool needmask = diag && (c == w);
            uint32_t pa[2][2][4];
#pragma unroll
            for (int m = 0; m < 2; m++) {
                const int r0g = qt * 128 + w * 32 + m * 16 + gr;
#pragma unroll
                for (int nt = 0; nt < 4; nt++) {
                    float s0 = sc[m][nt][0], s1 = sc[m][nt][1];
                    float s2 = sc[m][nt][2], s3 = sc[m][nt][3];
                    if (needmask) {
                        const int col = kstart + nt * 8 + tig * 2;
                        if (col     > r0g)     s0 = -3e4f;
                        if (col + 1 > r0g)     s1 = -3e4f;
                        if (col     > r0g + 8) s2 = -3e4f;
                        if (col + 1 > r0g + 8) s3 = -3e4f;
                    }
                    const int ks2 = nt >> 1, hf = nt & 1;
                    pa[m][ks2][2*hf]     = h2ex2(packh2(s0, s1));
                    pa[m][ks2][2*hf + 1] = h2ex2(packh2(s2, s3));
                }
            }

            // ---- l accumulation: HADD2 tree + f32 (replaces 4 HMMA + 2 LDSM) ----
#pragma unroll
            for (int m = 0; m < 2; m++) {
                uint32_t a0 = hadd2u(pa[m][0][0], pa[m][0][2]);
                uint32_t a1 = hadd2u(pa[m][1][0], pa[m][1][2]);
                float2 f0 = h2f2(hadd2u(a0, a1));
                lp[m][0] += f0.x + f0.y;
                uint32_t b0 = hadd2u(pa[m][0][1], pa[m][0][3]);
                uint32_t b1 = hadd2u(pa[m][1][1], pa[m][1][3]);
                float2 f1 = h2f2(hadd2u(b0, b1));
                lp[m][1] += f1.x + f1.y;
            }

            uint32_t vfb[2][2][2];
#pragma unroll
            for (int ks2 = 0; ks2 < 2; ks2++) {
                uint32_t vrow = c * 32 + ks2 * 16 + ((mi & 1) ? 8 : 0) + lr;
                uint32_t vcol = (mi & 2) ? 8 : 0;
                uint32_t r0, r1, r2, r3;
                ldsm_x4_t(vs_sm + (vrow * KSTR + vcol) * 2, r0, r1, r2, r3);
                vfb[ks2][0][0] = r0; vfb[ks2][0][1] = r1;
                vfb[ks2][1][0] = r2; vfb[ks2][1][1] = r3;
            }

#pragma unroll
            for (int m = 0; m < 2; m++)
#pragma unroll
                for (int ks2 = 0; ks2 < 2; ks2++)
#pragma unroll
                    for (int nt = 0; nt < 2; nt++)
                        hmma(of[m][nt], pa[m][ks2], vfb[ks2][nt], of[m][nt]);
        }
    }

    // ---- reduce l over the 4 tig lanes, normalize, write f16 ----
#pragma unroll
    for (int m = 0; m < 2; m++) {
        float l0 = lp[m][0];
        l0 += __shfl_xor_sync(0xFFFFFFFFu, l0, 1);
        l0 += __shfl_xor_sync(0xFFFFFFFFu, l0, 2);
        float l1 = lp[m][1];
        l1 += __shfl_xor_sync(0xFFFFFFFFu, l1, 1);
        l1 += __shfl_xor_sync(0xFFFFFFFFu, l1, 2);
        const float inv0 = 1.f / l0, inv1 = 1.f / l1;
        const int r0g = qt * 128 + w * 32 + m * 16 + gr;
        uint32_t* ob = (uint32_t*)g_attnh + ((size_t)b * TT + r0g) * 64;
#pragma unroll
        for (int nt = 0; nt < 2; nt++) {
            const int cu = h * 8 + nt * 4 + tig;
            ob[cu]            = packh2(of[m][nt][0] * inv0, of[m][nt][1] * inv0);
            ob[cu + 8 * 64]   = packh2(of[m][nt][2] * inv1, of[m][nt][3] * inv1);
        }
    }
}

// ---------------------------------------------------------------------------
// Kernel 3: output projection via HMMA + bias, smem-staged, f32 out.
// ---------------------------------------------------------------------------
__global__ void __launch_bounds__(128) proj_hmma_kernel(const float* __restrict__ Wp,
                                                        const float* __restrict__ bp,
                                                        float* __restrict__ out)
{
    __shared__ __align__(16) __half xs[32 * PSTR];
    __shared__ __align__(16) __half ws[128 * PSTR];
    const uint32_t xs_sm = smem_u32(xs);
    const uint32_t ws_sm = smem_u32(ws);

    const int m0 = blockIdx.x * 32;
    const int tid = threadIdx.x;
    const int lane = tid & 31;
    const int w = tid >> 5;
    const int n0 = w * 32;
    const int gr = lane >> 2, tig = lane & 3;
    const int lr = lane & 7,  mi = lane >> 3;

    {
        const uint4* asrc = (const uint4*)(g_attnh + (size_t)m0 * CC);
#pragma unroll
        for (int i = tid; i < 32 * 16; i += 128) {
            const int row = i >> 4, c8 = i & 15;
            *(uint4*)(xs + row * PSTR + c8 * 8) = asrc[i];
        }
        const float4* wsrc = (const float4*)Wp;
#pragma unroll
        for (int i = tid; i < 128 * 32; i += 128) {
            const int row = i >> 5, c4 = i & 31;
            float4 v = wsrc[i];
            *(uint2*)(ws + row * PSTR + c4 * 4) =
                make_uint2(packh2(v.x, v.y), packh2(v.z, v.w));
        }
    }
    __syncthreads();

    float acc[2][4][4];
#pragma unroll
    for (int m = 0; m < 2; m++)
#pragma unroll
        for (int nt = 0; nt < 4; nt++)
#pragma unroll
            for (int i = 0; i < 4; i++) acc[m][nt][i] = 0.f;

#pragma unroll
    for (int ks = 0; ks < 8; ks++) {
        uint32_t a[2][4];
#pragma unroll
        for (int m = 0; m < 2; m++)
            ldsm_x4(xs_sm + ((m * 16 + (lane & 15)) * PSTR + ks * 16 + (lane >> 4) * 8) * 2,
                    a[m][0], a[m][1], a[m][2], a[m][3]);
        uint32_t kfb[4][2];
#pragma unroll
        for (int p = 0; p < 2; p++) {
            uint32_t r0, r1, r2, r3;
            ldsm_x4(ws_sm + ((n0 + p * 16 + ((mi & 2) ? 8 : 0) + lr) * PSTR
                             + ks * 16 + (mi & 1) * 8) * 2, r0, r1, r2, r3);
            kfb[2*p][0]   = r0; kfb[2*p][1]   = r1;
            kfb[2*p+1][0] = r2; kfb[2*p+1][1] = r3;
        }
#pragma unroll
        for (int nt = 0; nt < 4; nt++) {
            hmma(acc[0][nt], a[0], kfb[nt], acc[0][nt]);
            hmma(acc[1][nt], a[1], kfb[nt], acc[1][nt]);
        }
    }

#pragma unroll
    for (int m = 0; m < 2; m++) {
        const int row = m0 + m * 16 + gr;
#pragma unroll
        for (int nt = 0; nt < 4; nt++) {
            const int col = n0 + nt * 8 + 2 * tig;
            const float b0 = bp[col], b1 = bp[col + 1];
            *(float2*)(out + (size_t)row * CC + col) =
                make_float2(acc[m][nt][0] + b0, acc[m][nt][1] + b1);
            *(float2*)(out + (size_t)(row + 8) * CC + col) =
                make_float2(acc[m][nt][2] + b0, acc[m][nt][3] + b1);
        }
    }
}

// ---------------------------------------------------------------------------
extern "C" void kernel_launch(void* const* d_in, const int* in_sizes, int n_in,
                              void* d_out, int out_size)
{
    const float* x  = (const float*)d_in[0];
    const float* Wk = (const float*)d_in[1];
    const float* Wq = (const float*)d_in[2];
    const float* Wv = (const float*)d_in[3];
    const float* Wp = (const float*)d_in[4];
    const float* bp = (const float*)d_in[5];
    float* out = (float*)d_out;

    qkv_hmma_kernel<<<dim3(NROWS / 32, 3), 128>>>(x, Wk, Wq, Wv);
    attn_mma_kernel<<<dim3(QTILES, HH, BB), 128>>>();
    proj_hmma_kernel<<<NROWS / 32, 128>>>(Wp, bp, out);
}

// round 8
// speedup vs baseline: 1.3243x; 1.3243x over previous
#include <cuda_runtime.h>
#include <cuda_fp16.h>
#include <stdint.h>

#define BB 2
#define TT 4096
#define CC 128
#define HH 8
#define DD 16
#define NROWS (BB*TT)   // 8192
#define QTILES (TT/128) // 32
#define KSTR 24         // attn smem row stride in halfs (48B) -> conflict-free ldmatrix
#define PSTR 136        // projection smem row stride in halfs (272B) -> conflict-free ldmatrix
#define SEG 8           // kv tiles per segment
#define NSEGMAX 4

// f16 scratch
__device__ __half g_qh[BB*HH*TT*DD];     // q (pre-scaled by 0.25*log2e)
__device__ __half g_kh[BB*HH*TT*DD];
__device__ __half g_vh[BB*HH*TT*DD];
__device__ __half g_attnh[NROWS*CC];     // attention output f16
// KV-split partials
__device__ float g_opart[(size_t)BB*HH*QTILES*NSEGMAX*128*DD];   // 16.8 MB
__device__ float g_lpart[(size_t)BB*HH*QTILES*NSEGMAX*128];

// ---------------- helpers ----------------
__device__ __forceinline__ uint32_t smem_u32(const void* p) {
    uint32_t a; asm("{ .reg .u64 t; cvta.to.shared.u64 t, %1; cvt.u32.u64 %0, t; }" : "=r"(a) : "l"(p));
    return a;
}
__device__ __forceinline__ uint32_t packh2(float lo, float hi) {
    uint32_t d; asm("cvt.rn.f16x2.f32 %0, %1, %2;" : "=r"(d) : "f"(hi), "f"(lo)); return d;
}
__device__ __forceinline__ uint32_t h2ex2(uint32_t x) {
    uint32_t r; asm("ex2.approx.f16x2 %0, %1;" : "=r"(r) : "r"(x)); return r;
}
__device__ __forceinline__ uint32_t hadd2u(uint32_t a, uint32_t b) {
    uint32_t r; asm("add.f16x2 %0, %1, %2;" : "=r"(r) : "r"(a), "r"(b)); return r;
}
__device__ __forceinline__ float2 h2f2(uint32_t v) {
    __half2 h = *(__half2*)&v;
    return __half22float2(h);
}
__device__ __forceinline__ void ldsm_x4(uint32_t addr, uint32_t& r0, uint32_t& r1,
                                        uint32_t& r2, uint32_t& r3) {
    asm volatile("ldmatrix.sync.aligned.m8n8.x4.shared.b16 {%0,%1,%2,%3}, [%4];"
                 : "=r"(r0), "=r"(r1), "=r"(r2), "=r"(r3) : "r"(addr));
}
__device__ __forceinline__ void ldsm_x4_t(uint32_t addr, uint32_t& r0, uint32_t& r1,
                                          uint32_t& r2, uint32_t& r3) {
    asm volatile("ldmatrix.sync.aligned.m8n8.x4.trans.shared.b16 {%0,%1,%2,%3}, [%4];"
                 : "=r"(r0), "=r"(r1), "=r"(r2), "=r"(r3) : "r"(addr));
}
__device__ __forceinline__ void hmma(float* d, const uint32_t* a, const uint32_t* b, const float* c) {
    asm volatile(
        "mma.sync.aligned.m16n8k16.row.col.f32.f16.f16.f32 "
        "{%0,%1,%2,%3}, {%4,%5,%6,%7}, {%8,%9}, {%10,%11,%12,%13};"
        : "=f"(d[0]), "=f"(d[1]), "=f"(d[2]), "=f"(d[3])
        : "r"(a[0]), "r"(a[1]), "r"(a[2]), "r"(a[3]),
          "r"(b[0]), "r"(b[1]),
          "f"(c[0]), "f"(c[1]), "f"(c[2]), "f"(c[3]));
}
__device__ __forceinline__ void cpa16(uint32_t dst, const void* src) {
    asm volatile("cp.async.cg.shared.global [%0], [%1], 16;" :: "r"(dst), "l"(src));
}
#define CP_COMMIT() asm volatile("cp.async.commit_group;" ::: "memory")
#define CP_WAIT0()  asm volatile("cp.async.wait_group 0;" ::: "memory")

// ---------------------------------------------------------------------------
// Kernel 1: QKV projection via HMMA, smem-staged (unchanged, ~12us)
// ---------------------------------------------------------------------------
__global__ void __launch_bounds__(128) qkv_hmma_kernel(const float* __restrict__ x,
                                                       const float* __restrict__ Wk,
                                                       const float* __restrict__ Wq,
                                                       const float* __restrict__ Wv)
{
    const int sel = blockIdx.y;
    const float* W = (sel == 0) ? Wq : (sel == 1) ? Wk : Wv;
    __half* dstH = (sel == 0) ? g_qh : (sel == 1) ? g_kh : g_vh;
    const float osc = (sel == 0) ? (0.25f * 1.44269504f) : 1.0f;

    __shared__ __align__(16) __half xs[32 * PSTR];
    __shared__ __align__(16) __half ws[128 * PSTR];
    const uint32_t xs_sm = smem_u32(xs);
    const uint32_t ws_sm = smem_u32(ws);

    const int m0 = blockIdx.x * 32;
    const int tid = threadIdx.x;
    const int lane = tid & 31;
    const int w = tid >> 5;
    const int n0 = w * 32;
    const int gr = lane >> 2, tig = lane & 3;
    const int lr = lane & 7,  mi = lane >> 3;

    {
        const float4* xsrc = (const float4*)(x + (size_t)m0 * CC);
#pragma unroll
        for (int i = tid; i < 32 * 32; i += 128) {
            const int row = i >> 5, c4 = i & 31;
            float4 v = xsrc[i];
            *(uint2*)(xs + row * PSTR + c4 * 4) =
                make_uint2(packh2(v.x, v.y), packh2(v.z, v.w));
        }
        const float4* wsrc = (const float4*)W;
#pragma unroll
        for (int i = tid; i < 128 * 32; i += 128) {
            const int row = i >> 5, c4 = i & 31;
            float4 v = wsrc[i];
            *(uint2*)(ws + row * PSTR + c4 * 4) =
                make_uint2(packh2(v.x, v.y), packh2(v.z, v.w));
        }
    }
    __syncthreads();

    float acc[2][4][4];
#pragma unroll
    for (int m = 0; m < 2; m++)
#pragma unroll
        for (int nt = 0; nt < 4; nt++)
#pragma unroll
            for (int i = 0; i < 4; i++) acc[m][nt][i] = 0.f;

#pragma unroll
    for (int ks = 0; ks < 8; ks++) {
        uint32_t a[2][4];
#pragma unroll
        for (int m = 0; m < 2; m++)
            ldsm_x4(xs_sm + ((m * 16 + (lane & 15)) * PSTR + ks * 16 + (lane >> 4) * 8) * 2,
                    a[m][0], a[m][1], a[m][2], a[m][3]);
        uint32_t kfb[4][2];
#pragma unroll
        for (int p = 0; p < 2; p++) {
            uint32_t r0, r1, r2, r3;
            ldsm_x4(ws_sm + ((n0 + p * 16 + ((mi & 2) ? 8 : 0) + lr) * PSTR
                             + ks * 16 + (mi & 1) * 8) * 2, r0, r1, r2, r3);
            kfb[2*p][0]   = r0; kfb[2*p][1]   = r1;
            kfb[2*p+1][0] = r2; kfb[2*p+1][1] = r3;
        }
#pragma unroll
        for (int nt = 0; nt < 4; nt++) {
            hmma(acc[0][nt], a[0], kfb[nt], acc[0][nt]);
            hmma(acc[1][nt], a[1], kfb[nt], acc[1][nt]);
        }
    }

    uint32_t* d32 = (uint32_t*)dstH;
#pragma unroll
    for (int m = 0; m < 2; m++) {
        const int row = m0 + m * 16 + gr;
        const int bb = row >> 12, t = row & (TT - 1);
#pragma unroll
        for (int nt = 0; nt < 4; nt++) {
            const int col = n0 + nt * 8 + 2 * tig;
            const int h = col >> 4, d = col & 15;
            const size_t idx = ((size_t)(bb * HH + h) * TT + t) * 8 + (d >> 1);
            d32[idx]      = packh2(acc[m][nt][0] * osc, acc[m][nt][1] * osc);
            d32[idx + 64] = packh2(acc[m][nt][2] * osc, acc[m][nt][3] * osc);
        }
    }
}

// ---------------------------------------------------------------------------
// Kernel 2: KV-split HMMA flash attention.  grid=(NSEGMAX, QTILES, HH*BB).
// Segment s handles kv tiles [s*SEG, min(s*SEG+SEG, qt+1)); partial O (f32)
// and l go to g_opart/g_lpart; combine_kernel sums them (no-max softmax =>
// partials combine by pure addition).
// ---------------------------------------------------------------------------
__global__ void __launch_bounds__(128) attn_mma_kernel()
{
    const int s   = blockIdx.x;
    const int qt  = blockIdx.y;
    const int bh  = blockIdx.z;
    if (s * SEG > qt) return;                    // inactive segment
    const int h   = bh & 7;
    const int b   = bh >> 3;
    const int tid = threadIdx.x;
    const int w   = tid >> 5;
    const int lane = tid & 31;
    const int gr  = lane >> 2;
    const int tig = lane & 3;
    const int lr  = lane & 7;
    const int mi  = lane >> 3;

    const int kt0 = s * SEG;
    const int kt1 = min(kt0 + SEG, qt + 1);

    __shared__ __align__(16) __half Ks[2][128 * KSTR];
    __shared__ __align__(16) __half Vs[2][128 * KSTR];
    const uint32_t ksb = smem_u32(Ks);
    const uint32_t vsb = smem_u32(Vs);
    const uint32_t BUFB = 128 * KSTR * 2;

    const size_t head = (size_t)bh * TT;
    const __half* kh = g_kh + head * DD;
    const __half* vh = g_vh + head * DD;

    // Q A-fragments (pre-scaled, pre-packed f16)
    uint32_t qa[2][4];
    {
        const uint32_t* qh32 = (const uint32_t*)g_qh + (head + (size_t)qt * 128) * 8;
#pragma unroll
        for (int m = 0; m < 2; m++) {
            const int base = (w * 32 + m * 16 + gr) * 8 + tig;
            qa[m][0] = qh32[base];     qa[m][1] = qh32[base + 64];
            qa[m][2] = qh32[base + 4]; qa[m][3] = qh32[base + 68];
        }
    }

    float of[2][2][4];
#pragma unroll
    for (int m = 0; m < 2; m++)
#pragma unroll
        for (int n = 0; n < 2; n++)
#pragma unroll
            for (int i = 0; i < 4; i++) of[m][n][i] = 0.f;
    float lp[2][2] = {{0.f, 0.f}, {0.f, 0.f}};
    const float zc[4] = {0.f, 0.f, 0.f, 0.f};

    const uint32_t krow_off = (uint32_t)tid * (KSTR * 2);

    // prefetch first tile
    {
        const __half* ksrc = kh + (size_t)(kt0 * 128 + tid) * DD;
        const __half* vsrc = vh + (size_t)(kt0 * 128 + tid) * DD;
        cpa16(ksb + krow_off,      ksrc);
        cpa16(ksb + krow_off + 16, ksrc + 8);
        cpa16(vsb + krow_off,      vsrc);
        cpa16(vsb + krow_off + 16, vsrc + 8);
        CP_COMMIT();
    }

    for (int kt = kt0; kt < kt1; kt++) {
        CP_WAIT0();
        __syncthreads();

        if (kt + 1 < kt1) {
            const uint32_t nb = ((kt + 1) & 1) * BUFB;
            const __half* ksrc = kh + (size_t)((kt + 1) * 128 + tid) * DD;
            const __half* vsrc = vh + (size_t)((kt + 1) * 128 + tid) * DD;
            cpa16(ksb + nb + krow_off,      ksrc);
            cpa16(ksb + nb + krow_off + 16, ksrc + 8);
            cpa16(vsb + nb + krow_off,      vsrc);
            cpa16(vsb + nb + krow_off + 16, vsrc + 8);
            CP_COMMIT();
        }

        const uint32_t ks_sm = ksb + (kt & 1) * BUFB;
        const uint32_t vs_sm = vsb + (kt & 1) * BUFB;
        const bool diag = (kt == qt);
        const int cmax = diag ? (w + 1) : 4;

#pragma unroll 4
        for (int c = 0; c < cmax; c++) {
            const int kstart = kt * 128 + c * 32;

            uint32_t kfb[4][2];
#pragma unroll
            for (int p = 0; p < 2; p++) {
                uint32_t krow = c * 32 + p * 16 + ((mi & 2) ? 8 : 0) + lr;
                uint32_t kcol = (mi & 1) * 8;
                uint32_t r0, r1, r2, r3;
                ldsm_x4(ks_sm + (krow * KSTR + kcol) * 2, r0, r1, r2, r3);
                kfb[2*p][0]   = r0; kfb[2*p][1]   = r1;
                kfb[2*p+1][0] = r2; kfb[2*p+1][1] = r3;
            }

            float sc[2][4][4];
#pragma unroll
            for (int m = 0; m < 2; m++)
#pragma unroll
                for (int nt = 0; nt < 4; nt++)
                    hmma(sc[m][nt], qa[m], kfb[nt], zc);

            const bool needmask = diag && (c == w);
            uint32_t pa[2][2][4];
#pragma unroll
            for (int m = 0; m < 2; m++) {
                const int r0g = qt * 128 + w * 32 + m * 16 + gr;
#pragma unroll
                for (int nt = 0; nt < 4; nt++) {
                    float s0 = sc[m][nt][0], s1 = sc[m][nt][1];
                    float s2 = sc[m][nt][2], s3 = sc[m][nt][3];
                    if (needmask) {
                        const int col = kstart + nt * 8 + tig * 2;
                        if (col     > r0g)     s0 = -3e4f;
                        if (col + 1 > r0g)     s1 = -3e4f;
                        if (col     > r0g + 8) s2 = -3e4f;
                        if (col + 1 > r0g + 8) s3 = -3e4f;
                    }
                    const int ks2 = nt >> 1, hf = nt & 1;
                    pa[m][ks2][2*hf]     = h2ex2(packh2(s0, s1));
                    pa[m][ks2][2*hf + 1] = h2ex2(packh2(s2, s3));
                }
            }

            // l accumulation: HADD2 tree + f32
#pragma unroll
            for (int m = 0; m < 2; m++) {
                uint32_t a0 = hadd2u(pa[m][0][0], pa[m][0][2]);
                uint32_t a1 = hadd2u(pa[m][1][0], pa[m][1][2]);
                float2 f0 = h2f2(hadd2u(a0, a1));
                lp[m][0] += f0.x + f0.y;
                uint32_t b0 = hadd2u(pa[m][0][1], pa[m][0][3]);
                uint32_t b1 = hadd2u(pa[m][1][1], pa[m][1][3]);
                float2 f1 = h2f2(hadd2u(b0, b1));
                lp[m][1] += f1.x + f1.y;
            }

            uint32_t vfb[2][2][2];
#pragma unroll
            for (int ks2 = 0; ks2 < 2; ks2++) {
                uint32_t vrow = c * 32 + ks2 * 16 + ((mi & 1) ? 8 : 0) + lr;
                uint32_t vcol = (mi & 2) ? 8 : 0;
                uint32_t r0, r1, r2, r3;
                ldsm_x4_t(vs_sm + (vrow * KSTR + vcol) * 2, r0, r1, r2, r3);
                vfb[ks2][0][0] = r0; vfb[ks2][0][1] = r1;
                vfb[ks2][1][0] = r2; vfb[ks2][1][1] = r3;
            }

#pragma unroll
            for (int m = 0; m < 2; m++)
#pragma unroll
                for (int ks2 = 0; ks2 < 2; ks2++)
#pragma unroll
                    for (int nt = 0; nt < 2; nt++)
                        hmma(of[m][nt], pa[m][ks2], vfb[ks2][nt], of[m][nt]);
        }
    }

    // ---- write partials: O (f32) and l ----
    const size_t seg = ((size_t)bh * QTILES + qt) * NSEGMAX + s;
    float* ob = g_opart + seg * 128 * DD;
#pragma unroll
    for (int m = 0; m < 2; m++) {
        const int row = w * 32 + m * 16 + gr;
#pragma unroll
        for (int nt = 0; nt < 2; nt++) {
            const int col = nt * 8 + 2 * tig;
            *(float2*)(ob + row * DD + col)       = make_float2(of[m][nt][0], of[m][nt][1]);
            *(float2*)(ob + (row + 8) * DD + col) = make_float2(of[m][nt][2], of[m][nt][3]);
        }
        float l0 = lp[m][0];
        l0 += __shfl_xor_sync(0xFFFFFFFFu, l0, 1);
        l0 += __shfl_xor_sync(0xFFFFFFFFu, l0, 2);
        float l1 = lp[m][1];
        l1 += __shfl_xor_sync(0xFFFFFFFFu, l1, 1);
        l1 += __shfl_xor_sync(0xFFFFFFFFu, l1, 2);
        if (tig == 0) {
            g_lpart[seg * 128 + row]     = l0;
            g_lpart[seg * 128 + row + 8] = l1;
        }
    }
}

// ---------------------------------------------------------------------------
// Kernel 2b: combine partials -> normalized f16 attn output.
// grid=512, block=128.  Thread = one (bh, t) row.
// ---------------------------------------------------------------------------
__global__ void __launch_bounds__(128) combine_kernel()
{
    const int slot = blockIdx.x * 128 + threadIdx.x;   // 0..65535
    const int bh = slot >> 12;
    const int t  = slot & (TT - 1);
    const int qt = t >> 7;
    const int r  = t & 127;
    const int nseg = (qt >> 3) + 1;

    const size_t segbase = ((size_t)bh * QTILES + qt) * NSEGMAX;
    float acc[DD];
#pragma unroll
    for (int i = 0; i < DD; i++) acc[i] = 0.f;
    float l = 0.f;

    for (int s = 0; s < nseg; s++) {
        const float4* p = (const float4*)(g_opart + (segbase + s) * 128 * DD + r * DD);
#pragma unroll
        for (int i = 0; i < 4; i++) {
            float4 v = p[i];
            acc[4*i]   += v.x; acc[4*i+1] += v.y;
            acc[4*i+2] += v.z; acc[4*i+3] += v.w;
        }
        l += g_lpart[(segbase + s) * 128 + r];
    }

    const float inv = 1.f / l;
    const int b = bh >> 3, h = bh & 7;
    uint32_t* ob = (uint32_t*)g_attnh + ((size_t)b * TT + t) * 64 + h * 8;
#pragma unroll
    for (int i = 0; i < 8; i++)
        ob[i] = packh2(acc[2*i] * inv, acc[2*i+1] * inv);
}

// ---------------------------------------------------------------------------
// Kernel 3: output projection via HMMA + bias, smem-staged, f32 out.
// ---------------------------------------------------------------------------
__global__ void __launch_bounds__(128) proj_hmma_kernel(const float* __restrict__ Wp,
                                                        const float* __restrict__ bp,
                                                        float* __restrict__ out)
{
    __shared__ __align__(16) __half xs[32 * PSTR];
    __shared__ __align__(16) __half ws[128 * PSTR];
    const uint32_t xs_sm = smem_u32(xs);
    const uint32_t ws_sm = smem_u32(ws);

    const int m0 = blockIdx.x * 32;
    const int tid = threadIdx.x;
    const int lane = tid & 31;
    const int w = tid >> 5;
    const int n0 = w * 32;
    const int gr = lane >> 2, tig = lane & 3;
    const int lr = lane & 7,  mi = lane >> 3;

    {
        const uint4* asrc = (const uint4*)(g_attnh + (size_t)m0 * CC);
#pragma unroll
        for (int i = tid; i < 32 * 16; i += 128) {
            const int row = i >> 4, c8 = i & 15;
            *(uint4*)(xs + row * PSTR + c8 * 8) = asrc[i];
        }
        const float4* wsrc = (const float4*)Wp;
#pragma unroll
        for (int i = tid; i < 128 * 32; i += 128) {
            const int row = i >> 5, c4 = i & 31;
            float4 v = wsrc[i];
            *(uint2*)(ws + row * PSTR + c4 * 4) =
                make_uint2(packh2(v.x, v.y), packh2(v.z, v.w));
        }
    }
    __syncthreads();

    float acc[2][4][4];
#pragma unroll
    for (int m = 0; m < 2; m++)
#pragma unroll
        for (int nt = 0; nt < 4; nt++)
#pragma unroll
            for (int i = 0; i < 4; i++) acc[m][nt][i] = 0.f;

#pragma unroll
    for (int ks = 0; ks < 8; ks++) {
        uint32_t a[2][4];
#pragma unroll
        for (int m = 0; m < 2; m++)
            ldsm_x4(xs_sm + ((m * 16 + (lane & 15)) * PSTR + ks * 16 + (lane >> 4) * 8) * 2,
                    a[m][0], a[m][1], a[m][2], a[m][3]);
        uint32_t kfb[4][2];
#pragma unroll
        for (int p = 0; p < 2; p++) {
            uint32_t r0, r1, r2, r3;
            ldsm_x4(ws_sm + ((n0 + p * 16 + ((mi & 2) ? 8 : 0) + lr) * PSTR
                             + ks * 16 + (mi & 1) * 8) * 2, r0, r1, r2, r3);
            kfb[2*p][0]   = r0; kfb[2*p][1]   = r1;
            kfb[2*p+1][0] = r2; kfb[2*p+1][1] = r3;
        }
#pragma unroll
        for (int nt = 0; nt < 4; nt++) {
            hmma(acc[0][nt], a[0], kfb[nt], acc[0][nt]);
            hmma(acc[1][nt], a[1], kfb[nt], acc[1][nt]);
        }
    }

#pragma unroll
    for (int m = 0; m < 2; m++) {
        const int row = m0 + m * 16 + gr;
#pragma unroll
        for (int nt = 0; nt < 4; nt++) {
            const int col = n0 + nt * 8 + 2 * tig;
            const float b0 = bp[col], b1 = bp[col + 1];
            *(float2*)(out + (size_t)row * CC + col) =
                make_float2(acc[m][nt][0] + b0, acc[m][nt][1] + b1);
            *(float2*)(out + (size_t)(row + 8) * CC + col) =
                make_float2(acc[m][nt][2] + b0, acc[m][nt][3] + b1);
        }
    }
}

// ---------------------------------------------------------------------------
extern "C" void kernel_launch(void* const* d_in, const int* in_sizes, int n_in,
                              void* d_out, int out_size)
{
    const float* x  = (const float*)d_in[0];
    const float* Wk = (const float*)d_in[1];
    const float* Wq = (const float*)d_in[2];
    const float* Wv = (const float*)d_in[3];
    const float* Wp = (const float*)d_in[4];
    const float* bp = (const float*)d_in[5];
    float* out = (float*)d_out;

    qkv_hmma_kernel<<<dim3(NROWS / 32, 3), 128>>>(x, Wk, Wq, Wv);
    attn_mma_kernel<<<dim3(NSEGMAX, QTILES, HH * BB), 128>>>();
    combine_kernel<<<NROWS * HH / 128, 128>>>();
    proj_hmma_kernel<<<NROWS / 32, 128>>>(Wp, bp, out);
}

// round 10
// speedup vs baseline: 1.3921x; 1.0512x over previous
#include <cuda_runtime.h>
#include <cuda_fp16.h>
#include <stdint.h>

#define BB 2
#define TT 4096
#define CC 128
#define HH 8
#define DD 16
#define NROWS (BB*TT)   // 8192
#define QTILES (TT/128) // 32
#define KSTR 24         // attn smem row stride in halfs (48B) -> conflict-free ldmatrix
#define PSTR 136        // projection smem row stride in halfs (272B) -> conflict-free ldmatrix
#define SEG 8           // kv tiles per segment
#define NSEGMAX 4
#define PROWS 64        // rows per projection CTA
#define PROJ_SMEM ((PROWS + 128) * PSTR * 2)   // 52224 bytes (dynamic)

// f16 scratch
__device__ __half g_qh[BB*HH*TT*DD];     // q (pre-scaled by 0.25*log2e)
__device__ __half g_kh[BB*HH*TT*DD];
__device__ __half g_vh[BB*HH*TT*DD];
__device__ __half g_attnh[NROWS*CC];     // attention output f16
// KV-split partials
__device__ float g_opart[(size_t)BB*HH*QTILES*NSEGMAX*128*DD];
__device__ float g_lpart[(size_t)BB*HH*QTILES*NSEGMAX*128];

// ---------------- helpers ----------------
__device__ __forceinline__ uint32_t smem_u32(const void* p) {
    uint32_t a; asm("{ .reg .u64 t; cvta.to.shared.u64 t, %1; cvt.u32.u64 %0, t; }" : "=r"(a) : "l"(p));
    return a;
}
__device__ __forceinline__ uint32_t packh2(float lo, float hi) {
    uint32_t d; asm("cvt.rn.f16x2.f32 %0, %1, %2;" : "=r"(d) : "f"(hi), "f"(lo)); return d;
}
__device__ __forceinline__ uint32_t h2ex2(uint32_t x) {
    uint32_t r; asm("ex2.approx.f16x2 %0, %1;" : "=r"(r) : "r"(x)); return r;
}
__device__ __forceinline__ uint32_t hadd2u(uint32_t a, uint32_t b) {
    uint32_t r; asm("add.f16x2 %0, %1, %2;" : "=r"(r) : "r"(a), "r"(b)); return r;
}
__device__ __forceinline__ float2 h2f2(uint32_t v) {
    __half2 h = *(__half2*)&v;
    return __half22float2(h);
}
__device__ __forceinline__ void ldsm_x4(uint32_t addr, uint32_t& r0, uint32_t& r1,
                                        uint32_t& r2, uint32_t& r3) {
    asm volatile("ldmatrix.sync.aligned.m8n8.x4.shared.b16 {%0,%1,%2,%3}, [%4];"
                 : "=r"(r0), "=r"(r1), "=r"(r2), "=r"(r3) : "r"(addr));
}
__device__ __forceinline__ void ldsm_x4_t(uint32_t addr, uint32_t& r0, uint32_t& r1,
                                          uint32_t& r2, uint32_t& r3) {
    asm volatile("ldmatrix.sync.aligned.m8n8.x4.trans.shared.b16 {%0,%1,%2,%3}, [%4];"
                 : "=r"(r0), "=r"(r1), "=r"(r2), "=r"(r3) : "r"(addr));
}
// fp32-accum HMMA
__device__ __forceinline__ void hmma(float* d, const uint32_t* a, const uint32_t* b, const float* c) {
    asm volatile(
        "mma.sync.aligned.m16n8k16.row.col.f32.f16.f16.f32 "
        "{%0,%1,%2,%3}, {%4,%5,%6,%7}, {%8,%9}, {%10,%11,%12,%13};"
        : "=f"(d[0]), "=f"(d[1]), "=f"(d[2]), "=f"(d[3])
        : "r"(a[0]), "r"(a[1]), "r"(a[2]), "r"(a[3]),
          "r"(b[0]), "r"(b[1]),
          "f"(c[0]), "f"(c[1]), "f"(c[2]), "f"(c[3]));
}
// f16-accum HMMA, zero C (for scores: output already packed f16x2)
__device__ __forceinline__ void hmma16z(uint32_t* d, const uint32_t* a, const uint32_t* b) {
    asm volatile(
        "mma.sync.aligned.m16n8k16.row.col.f16.f16.f16.f16 "
        "{%0,%1}, {%2,%3,%4,%5}, {%6,%7}, {%8,%9};"
        : "=r"(d[0]), "=r"(d[1])
        : "r"(a[0]), "r"(a[1]), "r"(a[2]), "r"(a[3]),
          "r"(b[0]), "r"(b[1]), "r"(0u), "r"(0u));
}
// mask pair of f16 (cols col, col+1 vs row): masked -> 0xF800 (-32768) so ex2 -> 0
__device__ __forceinline__ uint32_t maskpair(uint32_t v, int col, int row) {
    if (col     > row) v = (v & 0xFFFF0000u) | 0x0000F800u;
    if (col + 1 > row) v = (v & 0x0000FFFFu) | 0xF8000000u;
    return v;
}
__device__ __forceinline__ void cpa16(uint32_t dst, const void* src) {
    asm volatile("cp.async.cg.shared.global [%0], [%1], 16;" :: "r"(dst), "l"(src));
}
#define CP_COMMIT() asm volatile("cp.async.commit_group;" ::: "memory")
#define CP_WAIT0()  asm volatile("cp.async.wait_group 0;" ::: "memory")

// ---------------------------------------------------------------------------
// Kernel 1: QKV projection, 64 rows/CTA, 4 m-tiles per warp, dynamic smem.
// grid=(NROWS/PROWS, 3), block=128.
// ---------------------------------------------------------------------------
__global__ void __launch_bounds__(128) qkv_hmma_kernel(const float* __restrict__ x,
                                                       const float* __restrict__ Wk,
                                                       const float* __restrict__ Wq,
                                                       const float* __restrict__ Wv)
{
    const int sel = blockIdx.y;
    const float* W = (sel == 0) ? Wq : (sel == 1) ? Wk : Wv;
    __half* dstH = (sel == 0) ? g_qh : (sel == 1) ? g_kh : g_vh;
    const float osc = (sel == 0) ? (0.25f * 1.44269504f) : 1.0f;

    extern __shared__ __align__(16) __half dsm[];
    __half* xs = dsm;                    // PROWS x PSTR
    __half* ws = dsm + PROWS * PSTR;     // 128 x PSTR
    const uint32_t xs_sm = smem_u32(xs);
    const uint32_t ws_sm = smem_u32(ws);

    const int m0 = blockIdx.x * PROWS;
    const int tid = threadIdx.x;
    const int lane = tid & 31;
    const int w = tid >> 5;
    const int n0 = w * 32;
    const int gr = lane >> 2, tig = lane & 3;
    const int lr = lane & 7,  mi = lane >> 3;

    {
        const float4* xsrc = (const float4*)(x + (size_t)m0 * CC);
#pragma unroll
        for (int i = tid; i < PROWS * 32; i += 128) {
            const int row = i >> 5, c4 = i & 31;
            float4 v = xsrc[i];
            *(uint2*)(xs + row * PSTR + c4 * 4) =
                make_uint2(packh2(v.x, v.y), packh2(v.z, v.w));
        }
        const float4* wsrc = (const float4*)W;
#pragma unroll
        for (int i = tid; i < 128 * 32; i += 128) {
            const int row = i >> 5, c4 = i & 31;
            float4 v = wsrc[i];
            *(uint2*)(ws + row * PSTR + c4 * 4) =
                make_uint2(packh2(v.x, v.y), packh2(v.z, v.w));
        }
    }
    __syncthreads();

    float acc[4][4][4];
#pragma unroll
    for (int m = 0; m < 4; m++)
#pragma unroll
        for (int nt = 0; nt < 4; nt++)
#pragma unroll
            for (int i = 0; i < 4; i++) acc[m][nt][i] = 0.f;

#pragma unroll
    for (int ks = 0; ks < 8; ks++) {
        uint32_t a[4][4];
#pragma unroll
        for (int m = 0; m < 4; m++)
            ldsm_x4(xs_sm + ((m * 16 + (lane & 15)) * PSTR + ks * 16 + (lane >> 4) * 8) * 2,
                    a[m][0], a[m][1], a[m][2], a[m][3]);
        uint32_t kfb[4][2];
#pragma unroll
        for (int p = 0; p < 2; p++) {
            uint32_t r0, r1, r2, r3;
            ldsm_x4(ws_sm + ((n0 + p * 16 + ((mi & 2) ? 8 : 0) + lr) * PSTR
                             + ks * 16 + (mi & 1) * 8) * 2, r0, r1, r2, r3);
            kfb[2*p][0]   = r0; kfb[2*p][1]   = r1;
            kfb[2*p+1][0] = r2; kfb[2*p+1][1] = r3;
        }
#pragma unroll
        for (int nt = 0; nt < 4; nt++)
#pragma unroll
            for (int m = 0; m < 4; m++)
                hmma(acc[m][nt], a[m], kfb[nt], acc[m][nt]);
    }

    uint32_t* d32 = (uint32_t*)dstH;
#pragma unroll
    for (int m = 0; m < 4; m++) {
        const int row = m0 + m * 16 + gr;
        const int bb = row >> 12, t = row & (TT - 1);
#pragma unroll
        for (int nt = 0; nt < 4; nt++) {
            const int col = n0 + nt * 8 + 2 * tig;
            const int h = col >> 4, d = col & 15;
            const size_t idx = ((size_t)(bb * HH + h) * TT + t) * 8 + (d >> 1);
            d32[idx]      = packh2(acc[m][nt][0] * osc, acc[m][nt][1] * osc);
            d32[idx + 64] = packh2(acc[m][nt][2] * osc, acc[m][nt][3] * osc);
        }
    }
}

// ---------------------------------------------------------------------------
// Kernel 2: KV-split HMMA flash attention.  QK in f16-accum HMMA (S already
// packed f16x2 -> ex2 direct, no cvt).  PV + l stay f32.
// grid=(NSEGMAX, QTILES, HH*BB), block=128.
// ---------------------------------------------------------------------------
__global__ void __launch_bounds__(128) attn_mma_kernel()
{
    const int s   = blockIdx.x;
    const int qt  = blockIdx.y;
    const int bh  = blockIdx.z;
    if (s * SEG > qt) return;
    const int tid = threadIdx.x;
    const int w   = tid >> 5;
    const int lane = tid & 31;
    const int gr  = lane >> 2;
    const int tig = lane & 3;
    const int lr  = lane & 7;
    const int mi  = lane >> 3;

    const int kt0 = s * SEG;
    const int kt1 = min(kt0 + SEG, qt + 1);

    __shared__ __align__(16) __half Ks[2][128 * KSTR];
    __shared__ __align__(16) __half Vs[2][128 * KSTR];
    const uint32_t ksb = smem_u32(Ks);
    const uint32_t vsb = smem_u32(Vs);
    const uint32_t BUFB = 128 * KSTR * 2;

    const size_t head = (size_t)bh * TT;
    const __half* kh = g_kh + head * DD;
    const __half* vh = g_vh + head * DD;

    uint32_t qa[2][4];
    {
        const uint32_t* qh32 = (const uint32_t*)g_qh + (head + (size_t)qt * 128) * 8;
#pragma unroll
        for (int m = 0; m < 2; m++) {
            const int base = (w * 32 + m * 16 + gr) * 8 + tig;
            qa[m][0] = qh32[base];     qa[m][1] = qh32[base + 64];
            qa[m][2] = qh32[base + 4]; qa[m][3] = qh32[base + 68];
        }
    }

    float of[2][2][4];
#pragma unroll
    for (int m = 0; m < 2; m++)
#pragma unroll
        for (int n = 0; n < 2; n++)
#pragma unroll
            for (int i = 0; i < 4; i++) of[m][n][i] = 0.f;
    float lp[2][2] = {{0.f, 0.f}, {0.f, 0.f}};

    const uint32_t krow_off = (uint32_t)tid * (KSTR * 2);

    {
        const __half* ksrc = kh + (size_t)(kt0 * 128 + tid) * DD;
        const __half* vsrc = vh + (size_t)(kt0 * 128 + tid) * DD;
        cpa16(ksb + krow_off,      ksrc);
        cpa16(ksb + krow_off + 16, ksrc + 8);
        cpa16(vsb + krow_off,      vsrc);
        cpa16(vsb + krow_off + 16, vsrc + 8);
        CP_COMMIT();
    }

    for (int kt = kt0; kt < kt1; kt++) {
        CP_WAIT0();
        __syncthreads();

        if (kt + 1 < kt1) {
            const uint32_t nb = ((kt + 1) & 1) * BUFB;
            const __half* ksrc = kh + (size_t)((kt + 1) * 128 + tid) * DD;
            const __half* vsrc = vh + (size_t)((kt + 1) * 128 + tid) * DD;
            cpa16(ksb + nb + krow_off,      ksrc);
            cpa16(ksb + nb + krow_off + 16, ksrc + 8);
            cpa16(vsb + nb + krow_off,      vsrc);
            cpa16(vsb + nb + krow_off + 16, vsrc + 8);
            CP_COMMIT();
        }

        const uint32_t ks_sm = ksb + (kt & 1) * BUFB;
        const uint32_t vs_sm = vsb + (kt & 1) * BUFB;
        const bool diag = (kt == qt);
        const int cmax = diag ? (w + 1) : 4;

#pragma unroll 4
        for (int c = 0; c < cmax; c++) {
            const int kstart = kt * 128 + c * 32;

            uint32_t kfb[4][2];
#pragma unroll
            for (int p = 0; p < 2; p++) {
                uint32_t krow = c * 32 + p * 16 + ((mi & 2) ? 8 : 0) + lr;
                uint32_t kcol = (mi & 1) * 8;
                uint32_t r0, r1, r2, r3;
                ldsm_x4(ks_sm + (krow * KSTR + kcol) * 2, r0, r1, r2, r3);
                kfb[2*p][0]   = r0; kfb[2*p][1]   = r1;
                kfb[2*p+1][0] = r2; kfb[2*p+1][1] = r3;
            }

            // ---- S = Q*K^T in f16 accum; ex2 directly on output regs ----
            const bool needmask = diag && (c == w);
            uint32_t pa[2][2][4];
#pragma unroll
            for (int m = 0; m < 2; m++) {
                const int r0g = qt * 128 + w * 32 + m * 16 + gr;
#pragma unroll
                for (int nt = 0; nt < 4; nt++) {
                    uint32_t s2[2];
                    hmma16z(s2, qa[m], kfb[nt]);
                    if (needmask) {
                        const int col = kstart + nt * 8 + tig * 2;
                        s2[0] = maskpair(s2[0], col, r0g);
                        s2[1] = maskpair(s2[1], col, r0g + 8);
                    }
                    const int ks2 = nt >> 1, hf = nt & 1;
                    pa[m][ks2][2*hf]     = h2ex2(s2[0]);
                    pa[m][ks2][2*hf + 1] = h2ex2(s2[1]);
                }
            }

            // l accumulation: HADD2 tree + f32
#pragma unroll
            for (int m = 0; m < 2; m++) {
                uint32_t a0 = hadd2u(pa[m][0][0], pa[m][0][2]);
                uint32_t a1 = hadd2u(pa[m][1][0], pa[m][1][2]);
                float2 f0 = h2f2(hadd2u(a0, a1));
                lp[m][0] += f0.x + f0.y;
                uint32_t b0 = hadd2u(pa[m][0][1], pa[m][0][3]);
                uint32_t b1 = hadd2u(pa[m][1][1], pa[m][1][3]);
                float2 f1 = h2f2(hadd2u(b0, b1));
                lp[m][1] += f1.x + f1.y;
            }

            uint32_t vfb[2][2][2];
#pragma unroll
            for (int ks2 = 0; ks2 < 2; ks2++) {
                uint32_t vrow = c * 32 + ks2 * 16 + ((mi & 1) ? 8 : 0) + lr;
                uint32_t vcol = (mi & 2) ? 8 : 0;
                uint32_t r0, r1, r2, r3;
                ldsm_x4_t(vs_sm + (vrow * KSTR + vcol) * 2, r0, r1, r2, r3);
                vfb[ks2][0][0] = r0; vfb[ks2][0][1] = r1;
                vfb[ks2][1][0] = r2; vfb[ks2][1][1] = r3;
            }

#pragma unroll
            for (int m = 0; m < 2; m++)
#pragma unroll
                for (int ks2 = 0; ks2 < 2; ks2++)
#pragma unroll
                    for (int nt = 0; nt < 2; nt++)
                        hmma(of[m][nt], pa[m][ks2], vfb[ks2][nt], of[m][nt]);
        }
    }

    // ---- write partials ----
    const size_t seg = ((size_t)bh * QTILES + qt) * NSEGMAX + s;
    float* ob = g_opart + seg * 128 * DD;
#pragma unroll
    for (int m = 0; m < 2; m++) {
        const int row = w * 32 + m * 16 + gr;
#pragma unroll
        for (int nt = 0; nt < 2; nt++) {
            const int col = nt * 8 + 2 * tig;
            *(float2*)(ob + row * DD + col)       = make_float2(of[m][nt][0], of[m][nt][1]);
            *(float2*)(ob + (row + 8) * DD + col) = make_float2(of[m][nt][2], of[m][nt][3]);
        }
        float l0 = lp[m][0];
        l0 += __shfl_xor_sync(0xFFFFFFFFu, l0, 1);
        l0 += __shfl_xor_sync(0xFFFFFFFFu, l0, 2);
        float l1 = lp[m][1];
        l1 += __shfl_xor_sync(0xFFFFFFFFu, l1, 1);
        l1 += __shfl_xor_sync(0xFFFFFFFFu, l1, 2);
        if (tig == 0) {
            g_lpart[seg * 128 + row]     = l0;
            g_lpart[seg * 128 + row + 8] = l1;
        }
    }
}

// ---------------------------------------------------------------------------
// Kernel 2b: combine partials -> normalized f16 attn output.
// ---------------------------------------------------------------------------
__global__ void __launch_bounds__(128) combine_kernel()
{
    const int slot = blockIdx.x * 128 + threadIdx.x;
    const int bh = slot >> 12;
    const int t  = slot & (TT - 1);
    const int qt = t >> 7;
    const int r  = t & 127;
    const int nseg = (qt >> 3) + 1;

    const size_t segbase = ((size_t)bh * QTILES + qt) * NSEGMAX;
    float acc[DD];
#pragma unroll
    for (int i = 0; i < DD; i++) acc[i] = 0.f;
    float l = 0.f;

    for (int s = 0; s < nseg; s++) {
        const float4* p = (const float4*)(g_opart + (segbase + s) * 128 * DD + r * DD);
#pragma unroll
        for (int i = 0; i < 4; i++) {
            float4 v = p[i];
            acc[4*i]   += v.x; acc[4*i+1] += v.y;
            acc[4*i+2] += v.z; acc[4*i+3] += v.w;
        }
        l += g_lpart[(segbase + s) * 128 + r];
    }

    const float inv = 1.f / l;
    const int b = bh >> 3, h = bh & 7;
    uint32_t* ob = (uint32_t*)g_attnh + ((size_t)b * TT + t) * 64 + h * 8;
#pragma unroll
    for (int i = 0; i < 8; i++)
        ob[i] = packh2(acc[2*i] * inv, acc[2*i+1] * inv);
}

// ---------------------------------------------------------------------------
// Kernel 3: output projection, 64 rows/CTA, 4 m-tiles per warp, dynamic smem.
// grid=NROWS/PROWS, block=128.
// ---------------------------------------------------------------------------
__global__ void __launch_bounds__(128) proj_hmma_kernel(const float* __restrict__ Wp,
                                                        const float* __restrict__ bp,
                                                        float* __restrict__ out)
{
    extern __shared__ __align__(16) __half dsm[];
    __half* xs = dsm;
    __half* ws = dsm + PROWS * PSTR;
    const uint32_t xs_sm = smem_u32(xs);
    const uint32_t ws_sm = smem_u32(ws);

    const int m0 = blockIdx.x * PROWS;
    const int tid = threadIdx.x;
    const int lane = tid & 31;
    const int w = tid >> 5;
    const int n0 = w * 32;
    const int gr = lane >> 2, tig = lane & 3;
    const int lr = lane & 7,  mi = lane >> 3;

    {
        const uint4* asrc = (const uint4*)(g_attnh + (size_t)m0 * CC);
#pragma unroll
        for (int i = tid; i < PROWS * 16; i += 128) {
            const int row = i >> 4, c8 = i & 15;
            *(uint4*)(xs + row * PSTR + c8 * 8) = asrc[i];
        }
        const float4* wsrc = (const float4*)Wp;
#pragma unroll
        for (int i = tid; i < 128 * 32; i += 128) {
            const int row = i >> 5, c4 = i & 31;
            float4 v = wsrc[i];
            *(uint2*)(ws + row * PSTR + c4 * 4) =
                make_uint2(packh2(v.x, v.y), packh2(v.z, v.w));
        }
    }
    __syncthreads();

    float acc[4][4][4];
#pragma unroll
    for (int m = 0; m < 4; m++)
#pragma unroll
        for (int nt = 0; nt < 4; nt++)
#pragma unroll
            for (int i = 0; i < 4; i++) acc[m][nt][i] = 0.f;

#pragma unroll
    for (int ks = 0; ks < 8; ks++) {
        uint32_t a[4][4];
#pragma unroll
        for (int m = 0; m < 4; m++)
            ldsm_x4(xs_sm + ((m * 16 + (lane & 15)) * PSTR + ks * 16 + (lane >> 4) * 8) * 2,
                    a[m][0], a[m][1], a[m][2], a[m][3]);
        uint32_t kfb[4][2];
#pragma unroll
        for (int p = 0; p < 2; p++) {
            uint32_t r0, r1, r2, r3;
            ldsm_x4(ws_sm + ((n0 + p * 16 + ((mi & 2) ? 8 : 0) + lr) * PSTR
                             + ks * 16 + (mi & 1) * 8) * 2, r0, r1, r2, r3);
            kfb[2*p][0]   = r0; kfb[2*p][1]   = r1;
            kfb[2*p+1][0] = r2; kfb[2*p+1][1] = r3;
        }
#pragma unroll
        for (int nt = 0; nt < 4; nt++)
#pragma unroll
            for (int m = 0; m < 4; m++)
                hmma(acc[m][nt], a[m], kfb[nt], acc[m][nt]);
    }

#pragma unroll
    for (int m = 0; m < 4; m++) {
        const int row = m0 + m * 16 + gr;
#pragma unroll
        for (int nt = 0; nt < 4; nt++) {
            const int col = n0 + nt * 8 + 2 * tig;
            const float b0 = bp[col], b1 = bp[col + 1];
            *(float2*)(out + (size_t)row * CC + col) =
                make_float2(acc[m][nt][0] + b0, acc[m][nt][1] + b1);
            *(float2*)(out + (size_t)(row + 8) * CC + col) =
                make_float2(acc[m][nt][2] + b0, acc[m][nt][3] + b1);
        }
    }
}

// ---------------------------------------------------------------------------
extern "C" void kernel_launch(void* const* d_in, const int* in_sizes, int n_in,
                              void* d_out, int out_size)
{
    const float* x  = (const float*)d_in[0];
    const float* Wk = (const float*)d_in[1];
    const float* Wq = (const float*)d_in[2];
    const float* Wv = (const float*)d_in[3];
    const float* Wp = (const float*)d_in[4];
    const float* bp = (const float*)d_in[5];
    float* out = (float*)d_out;

    // opt into >48KB dynamic smem (host API, not a capture-stream op; idempotent)
    static bool attr_done = false;
    if (!attr_done) {
        cudaFuncSetAttribute(qkv_hmma_kernel,
                             cudaFuncAttributeMaxDynamicSharedMemorySize, PROJ_SMEM);
        cudaFuncSetAttribute(proj_hmma_kernel,
                             cudaFuncAttributeMaxDynamicSharedMemorySize, PROJ_SMEM);
        attr_done = true;
    }

    qkv_hmma_kernel<<<dim3(NROWS / PROWS, 3), 128, PROJ_SMEM>>>(x, Wk, Wq, Wv);
    attn_mma_kernel<<<dim3(NSEGMAX, QTILES, HH * BB), 128>>>();
    combine_kernel<<<NROWS * HH / 128, 128>>>();
    proj_hmma_kernel<<<NROWS / PROWS, 128, PROJ_SMEM>>>(Wp, bp, out);
}

// round 11
// speedup vs baseline: 1.4886x; 1.0693x over previous
#include <cuda_runtime.h>
#include <cuda_fp16.h>
#include <stdint.h>

#define BB 2
#define TT 4096
#define CC 128
#define HH 8
#define DD 16
#define NROWS (BB*TT)   // 8192
#define QTILES (TT/128) // 32
#define KSTR 24         // attn smem row stride in halfs (48B) -> conflict-free ldmatrix
#define PSTR 136        // projection smem row stride in halfs (272B) -> conflict-free ldmatrix
#define SEG 8           // kv tiles per segment
#define NSEGMAX 4
#define PROWS 64        // rows per projection CTA
#define PROJ_SMEM ((PROWS + 128) * PSTR * 2)   // 52224 bytes (dynamic)

// f16 scratch
__device__ __half g_qh[BB*HH*TT*DD];     // q (pre-scaled by 0.25*log2e)
__device__ __half g_kh[BB*HH*TT*DD];
__device__ __half g_vh[BB*HH*TT*DD];
__device__ __half g_attnh[NROWS*CC];     // attention output f16
// KV-split partials
__device__ float g_opart[(size_t)BB*HH*QTILES*NSEGMAX*128*DD];
__device__ float g_lpart[(size_t)BB*HH*QTILES*NSEGMAX*128];

// ---------------- helpers ----------------
__device__ __forceinline__ uint32_t smem_u32(const void* p) {
    uint32_t a; asm("{ .reg .u64 t; cvta.to.shared.u64 t, %1; cvt.u32.u64 %0, t; }" : "=r"(a) : "l"(p));
    return a;
}
__device__ __forceinline__ uint32_t packh2(float lo, float hi) {
    uint32_t d; asm("cvt.rn.f16x2.f32 %0, %1, %2;" : "=r"(d) : "f"(hi), "f"(lo)); return d;
}
__device__ __forceinline__ uint32_t h2ex2(uint32_t x) {
    uint32_t r; asm("ex2.approx.f16x2 %0, %1;" : "=r"(r) : "r"(x)); return r;
}
__device__ __forceinline__ uint32_t hadd2u(uint32_t a, uint32_t b) {
    uint32_t r; asm("add.f16x2 %0, %1, %2;" : "=r"(r) : "r"(a), "r"(b)); return r;
}
__device__ __forceinline__ float2 h2f2(uint32_t v) {
    __half2 h = *(__half2*)&v;
    return __half22float2(h);
}
__device__ __forceinline__ void ldsm_x4(uint32_t addr, uint32_t& r0, uint32_t& r1,
                                        uint32_t& r2, uint32_t& r3) {
    asm volatile("ldmatrix.sync.aligned.m8n8.x4.shared.b16 {%0,%1,%2,%3}, [%4];"
                 : "=r"(r0), "=r"(r1), "=r"(r2), "=r"(r3) : "r"(addr));
}
__device__ __forceinline__ void ldsm_x4_t(uint32_t addr, uint32_t& r0, uint32_t& r1,
                                          uint32_t& r2, uint32_t& r3) {
    asm volatile("ldmatrix.sync.aligned.m8n8.x4.trans.shared.b16 {%0,%1,%2,%3}, [%4];"
                 : "=r"(r0), "=r"(r1), "=r"(r2), "=r"(r3) : "r"(addr));
}
// fp32-accum HMMA
__device__ __forceinline__ void hmma(float* d, const uint32_t* a, const uint32_t* b, const float* c) {
    asm volatile(
        "mma.sync.aligned.m16n8k16.row.col.f32.f16.f16.f32 "
        "{%0,%1,%2,%3}, {%4,%5,%6,%7}, {%8,%9}, {%10,%11,%12,%13};"
        : "=f"(d[0]), "=f"(d[1]), "=f"(d[2]), "=f"(d[3])
        : "r"(a[0]), "r"(a[1]), "r"(a[2]), "r"(a[3]),
          "r"(b[0]), "r"(b[1]),
          "f"(c[0]), "f"(c[1]), "f"(c[2]), "f"(c[3]));
}
// f16-accum HMMA, zero C (for scores: output already packed f16x2)
__device__ __forceinline__ void hmma16z(uint32_t* d, const uint32_t* a, const uint32_t* b) {
    asm volatile(
        "mma.sync.aligned.m16n8k16.row.col.f16.f16.f16.f16 "
        "{%0,%1}, {%2,%3,%4,%5}, {%6,%7}, {%8,%9};"
        : "=r"(d[0]), "=r"(d[1])
        : "r"(a[0]), "r"(a[1]), "r"(a[2]), "r"(a[3]),
          "r"(b[0]), "r"(b[1]), "r"(0u), "r"(0u));
}
// mask pair of f16 (cols col, col+1 vs row): masked -> 0xF800 (-32768) so ex2 -> 0
__device__ __forceinline__ uint32_t maskpair(uint32_t v, int col, int row) {
    if (col     > row) v = (v & 0xFFFF0000u) | 0x0000F800u;
    if (col + 1 > row) v = (v & 0x0000FFFFu) | 0xF8000000u;
    return v;
}
__device__ __forceinline__ void cpa16(uint32_t dst, const void* src) {
    asm volatile("cp.async.cg.shared.global [%0], [%1], 16;" :: "r"(dst), "l"(src));
}
#define CP_COMMIT() asm volatile("cp.async.commit_group;" ::: "memory")
#define CP_WAIT0()  asm volatile("cp.async.wait_group 0;" ::: "memory")

// ---------------------------------------------------------------------------
// Kernel 1: QKV projection, 64 rows/CTA, 4 m-tiles per warp, dynamic smem.
// grid=(NROWS/PROWS, 3), block=128.
// ---------------------------------------------------------------------------
__global__ void __launch_bounds__(128) qkv_hmma_kernel(const float* __restrict__ x,
                                                       const float* __restrict__ Wk,
                                                       const float* __restrict__ Wq,
                                                       const float* __restrict__ Wv)
{
    const int sel = blockIdx.y;
    const float* W = (sel == 0) ? Wq : (sel == 1) ? Wk : Wv;
    __half* dstH = (sel == 0) ? g_qh : (sel == 1) ? g_kh : g_vh;
    const float osc = (sel == 0) ? (0.25f * 1.44269504f) : 1.0f;

    extern __shared__ __align__(16) __half dsm[];
    __half* xs = dsm;
    __half* ws = dsm + PROWS * PSTR;
    const uint32_t xs_sm = smem_u32(xs);
    const uint32_t ws_sm = smem_u32(ws);

    const int m0 = blockIdx.x * PROWS;
    const int tid = threadIdx.x;
    const int lane = tid & 31;
    const int w = tid >> 5;
    const int n0 = w * 32;
    const int gr = lane >> 2, tig = lane & 3;
    const int lr = lane & 7,  mi = lane >> 3;

    {
        const float4* xsrc = (const float4*)(x + (size_t)m0 * CC);
#pragma unroll
        for (int i = tid; i < PROWS * 32; i += 128) {
            const int row = i >> 5, c4 = i & 31;
            float4 v = xsrc[i];
            *(uint2*)(xs + row * PSTR + c4 * 4) =
                make_uint2(packh2(v.x, v.y), packh2(v.z, v.w));
        }
        const float4* wsrc = (const float4*)W;
#pragma unroll
        for (int i = tid; i < 128 * 32; i += 128) {
            const int row = i >> 5, c4 = i & 31;
            float4 v = wsrc[i];
            *(uint2*)(ws + row * PSTR + c4 * 4) =
                make_uint2(packh2(v.x, v.y), packh2(v.z, v.w));
        }
    }
    __syncthreads();

    float acc[4][4][4];
#pragma unroll
    for (int m = 0; m < 4; m++)
#pragma unroll
        for (int nt = 0; nt < 4; nt++)
#pragma unroll
            for (int i = 0; i < 4; i++) acc[m][nt][i] = 0.f;

#pragma unroll
    for (int ks = 0; ks < 8; ks++) {
        uint32_t a[4][4];
#pragma unroll
        for (int m = 0; m < 4; m++)
            ldsm_x4(xs_sm + ((m * 16 + (lane & 15)) * PSTR + ks * 16 + (lane >> 4) * 8) * 2,
                    a[m][0], a[m][1], a[m][2], a[m][3]);
        uint32_t kfb[4][2];
#pragma unroll
        for (int p = 0; p < 2; p++) {
            uint32_t r0, r1, r2, r3;
            ldsm_x4(ws_sm + ((n0 + p * 16 + ((mi & 2) ? 8 : 0) + lr) * PSTR
                             + ks * 16 + (mi & 1) * 8) * 2, r0, r1, r2, r3);
            kfb[2*p][0]   = r0; kfb[2*p][1]   = r1;
            kfb[2*p+1][0] = r2; kfb[2*p+1][1] = r3;
        }
#pragma unroll
        for (int nt = 0; nt < 4; nt++)
#pragma unroll
            for (int m = 0; m < 4; m++)
                hmma(acc[m][nt], a[m], kfb[nt], acc[m][nt]);
    }

    uint32_t* d32 = (uint32_t*)dstH;
#pragma unroll
    for (int m = 0; m < 4; m++) {
        const int row = m0 + m * 16 + gr;
        const int bb = row >> 12, t = row & (TT - 1);
#pragma unroll
        for (int nt = 0; nt < 4; nt++) {
            const int col = n0 + nt * 8 + 2 * tig;
            const int h = col >> 4, d = col & 15;
            const size_t idx = ((size_t)(bb * HH + h) * TT + t) * 8 + (d >> 1);
            d32[idx]      = packh2(acc[m][nt][0] * osc, acc[m][nt][1] * osc);
            d32[idx + 64] = packh2(acc[m][nt][2] * osc, acc[m][nt][3] * osc);
        }
    }
}

// ---------------------------------------------------------------------------
// Kernel 2: KV-split HMMA flash attention.  256 threads / 8 warps; each warp
// owns 16 query rows (halved dependent chains, 2x warps for latency hiding).
// QK f16-accum, ex2 direct; PV + l in f32.
// grid=(NSEGMAX, QTILES, HH*BB), block=256.
// ---------------------------------------------------------------------------
__global__ void __launch_bounds__(256) attn_mma_kernel()
{
    const int s   = blockIdx.x;
    const int qt  = blockIdx.y;
    const int bh  = blockIdx.z;
    if (s * SEG > qt) return;
    const int tid = threadIdx.x;
    const int w   = tid >> 5;          // 0..7, owns rows w*16..w*16+15
    const int lane = tid & 31;
    const int gr  = lane >> 2;
    const int tig = lane & 3;
    const int lr  = lane & 7;
    const int mi  = lane >> 3;

    const int kt0 = s * SEG;
    const int kt1 = min(kt0 + SEG, qt + 1);

    __shared__ __align__(16) __half Ks[2][128 * KSTR];
    __shared__ __align__(16) __half Vs[2][128 * KSTR];
    const uint32_t ksb = smem_u32(Ks);
    const uint32_t vsb = smem_u32(Vs);
    const uint32_t BUFB = 128 * KSTR * 2;

    const size_t head = (size_t)bh * TT;
    const __half* kh = g_kh + head * DD;
    const __half* vh = g_vh + head * DD;

    // Q A-fragments for this warp's single 16-row m-tile
    uint32_t qa[4];
    {
        const uint32_t* qh32 = (const uint32_t*)g_qh + (head + (size_t)qt * 128) * 8;
        const int base = (w * 16 + gr) * 8 + tig;
        qa[0] = qh32[base];     qa[1] = qh32[base + 64];
        qa[2] = qh32[base + 4]; qa[3] = qh32[base + 68];
    }

    float of[2][4];
#pragma unroll
    for (int n = 0; n < 2; n++)
#pragma unroll
        for (int i = 0; i < 4; i++) of[n][i] = 0.f;
    float lp[2] = {0.f, 0.f};

    // staging: 2 threads per row, 16B each
    const int srow = tid >> 1;
    const int soff = (tid & 1) * 16;   // bytes
    const uint32_t sdst = (uint32_t)srow * (KSTR * 2) + soff;
    const int ssrc = srow * DD + (tid & 1) * 8;

    {
        cpa16(ksb + sdst, kh + (size_t)kt0 * 128 * DD + ssrc);
        cpa16(vsb + sdst, vh + (size_t)kt0 * 128 * DD + ssrc);
        CP_COMMIT();
    }

    for (int kt = kt0; kt < kt1; kt++) {
        CP_WAIT0();
        __syncthreads();

        if (kt + 1 < kt1) {
            const uint32_t nb = ((kt + 1) & 1) * BUFB;
            cpa16(ksb + nb + sdst, kh + (size_t)(kt + 1) * 128 * DD + ssrc);
            cpa16(vsb + nb + sdst, vh + (size_t)(kt + 1) * 128 * DD + ssrc);
            CP_COMMIT();
        }

        const uint32_t ks_sm = ksb + (kt & 1) * BUFB;
        const uint32_t vs_sm = vsb + (kt & 1) * BUFB;
        const bool diag = (kt == qt);
        const int cmax = diag ? ((w >> 1) + 1) : 4;

#pragma unroll 4
        for (int c = 0; c < cmax; c++) {
            const int kstart = kt * 128 + c * 32;

            uint32_t kfb[4][2];
#pragma unroll
            for (int p = 0; p < 2; p++) {
                uint32_t krow = c * 32 + p * 16 + ((mi & 2) ? 8 : 0) + lr;
                uint32_t kcol = (mi & 1) * 8;
                uint32_t r0, r1, r2, r3;
                ldsm_x4(ks_sm + (krow * KSTR + kcol) * 2, r0, r1, r2, r3);
                kfb[2*p][0]   = r0; kfb[2*p][1]   = r1;
                kfb[2*p+1][0] = r2; kfb[2*p+1][1] = r3;
            }

            // S = Q*K^T (f16 accum), mask, ex2 -> P A-fragments
            const bool needmask = diag && (c == cmax - 1);
            const int r0g = qt * 128 + w * 16 + gr;
            uint32_t pa[2][4];
#pragma unroll
            for (int nt = 0; nt < 4; nt++) {
                uint32_t s2[2];
                hmma16z(s2, qa, kfb[nt]);
                if (needmask) {
                    const int col = kstart + nt * 8 + tig * 2;
                    s2[0] = maskpair(s2[0], col, r0g);
                    s2[1] = maskpair(s2[1], col, r0g + 8);
                }
                const int ks2 = nt >> 1, hf = nt & 1;
                pa[ks2][2*hf]     = h2ex2(s2[0]);
                pa[ks2][2*hf + 1] = h2ex2(s2[1]);
            }

            // l accumulation: HADD2 tree + f32
            {
                uint32_t a0 = hadd2u(pa[0][0], pa[0][2]);
                uint32_t a1 = hadd2u(pa[1][0], pa[1][2]);
                float2 f0 = h2f2(hadd2u(a0, a1));
                lp[0] += f0.x + f0.y;
                uint32_t b0 = hadd2u(pa[0][1], pa[0][3]);
                uint32_t b1 = hadd2u(pa[1][1], pa[1][3]);
                float2 f1 = h2f2(hadd2u(b0, b1));
                lp[1] += f1.x + f1.y;
            }

            uint32_t vfb[2][2][2];
#pragma unroll
            for (int ks2 = 0; ks2 < 2; ks2++) {
                uint32_t vrow = c * 32 + ks2 * 16 + ((mi & 1) ? 8 : 0) + lr;
                uint32_t vcol = (mi & 2) ? 8 : 0;
                uint32_t r0, r1, r2, r3;
                ldsm_x4_t(vs_sm + (vrow * KSTR + vcol) * 2, r0, r1, r2, r3);
                vfb[ks2][0][0] = r0; vfb[ks2][0][1] = r1;
                vfb[ks2][1][0] = r2; vfb[ks2][1][1] = r3;
            }

#pragma unroll
            for (int ks2 = 0; ks2 < 2; ks2++)
#pragma unroll
                for (int nt = 0; nt < 2; nt++)
                    hmma(of[nt], pa[ks2], vfb[ks2][nt], of[nt]);
        }
    }

    // ---- write partials ----
    const size_t seg = ((size_t)bh * QTILES + qt) * NSEGMAX + s;
    float* ob = g_opart + seg * 128 * DD;
    {
        const int row = w * 16 + gr;
#pragma unroll
        for (int nt = 0; nt < 2; nt++) {
            const int col = nt * 8 + 2 * tig;
            *(float2*)(ob + row * DD + col)       = make_float2(of[nt][0], of[nt][1]);
            *(float2*)(ob + (row + 8) * DD + col) = make_float2(of[nt][2], of[nt][3]);
        }
        float l0 = lp[0];
        l0 += __shfl_xor_sync(0xFFFFFFFFu, l0, 1);
        l0 += __shfl_xor_sync(0xFFFFFFFFu, l0, 2);
        float l1 = lp[1];
        l1 += __shfl_xor_sync(0xFFFFFFFFu, l1, 1);
        l1 += __shfl_xor_sync(0xFFFFFFFFu, l1, 2);
        if (tig == 0) {
            g_lpart[seg * 128 + row]     = l0;
            g_lpart[seg * 128 + row + 8] = l1;
        }
    }
}

// ---------------------------------------------------------------------------
// Kernel 2b: combine partials -> normalized f16 attn output.
// ---------------------------------------------------------------------------
__global__ void __launch_bounds__(128) combine_kernel()
{
    const int slot = blockIdx.x * 128 + threadIdx.x;
    const int bh = slot >> 12;
    const int t  = slot & (TT - 1);
    const int qt = t >> 7;
    const int r  = t & 127;
    const int nseg = (qt >> 3) + 1;

    const size_t segbase = ((size_t)bh * QTILES + qt) * NSEGMAX;
    float acc[DD];
#pragma unroll
    for (int i = 0; i < DD; i++) acc[i] = 0.f;
    float l = 0.f;

    for (int s = 0; s < nseg; s++) {
        const float4* p = (const float4*)(g_opart + (segbase + s) * 128 * DD + r * DD);
#pragma unroll
        for (int i = 0; i < 4; i++) {
            float4 v = p[i];
            acc[4*i]   += v.x; acc[4*i+1] += v.y;
            acc[4*i+2] += v.z; acc[4*i+3] += v.w;
        }
        l += g_lpart[(segbase + s) * 128 + r];
    }

    const float inv = 1.f / l;
    const int b = bh >> 3, h = bh & 7;
    uint32_t* ob = (uint32_t*)g_attnh + ((size_t)b * TT + t) * 64 + h * 8;
#pragma unroll
    for (int i = 0; i < 8; i++)
        ob[i] = packh2(acc[2*i] * inv, acc[2*i+1] * inv);
}

// ---------------------------------------------------------------------------
// Kernel 3: output projection, 64 rows/CTA, 4 m-tiles per warp, dynamic smem.
// ---------------------------------------------------------------------------
__global__ void __launch_bounds__(128) proj_hmma_kernel(const float* __restrict__ Wp,
                                                        const float* __restrict__ bp,
                                                        float* __restrict__ out)
{
    extern __shared__ __align__(16) __half dsm[];
    __half* xs = dsm;
    __half* ws = dsm + PROWS * PSTR;
    const uint32_t xs_sm = smem_u32(xs);
    const uint32_t ws_sm = smem_u32(ws);

    const int m0 = blockIdx.x * PROWS;
    const int tid = threadIdx.x;
    const int lane = tid & 31;
    const int w = tid >> 5;
    const int n0 = w * 32;
    const int gr = lane >> 2, tig = lane & 3;
    const int lr = lane & 7,  mi = lane >> 3;

    {
        const uint4* asrc = (const uint4*)(g_attnh + (size_t)m0 * CC);
#pragma unroll
        for (int i = tid; i < PROWS * 16; i += 128) {
            const int row = i >> 4, c8 = i & 15;
            *(uint4*)(xs + row * PSTR + c8 * 8) = asrc[i];
        }
        const float4* wsrc = (const float4*)Wp;
#pragma unroll
        for (int i = tid; i < 128 * 32; i += 128) {
            const int row = i >> 5, c4 = i & 31;
            float4 v = wsrc[i];
            *(uint2*)(ws + row * PSTR + c4 * 4) =
                make_uint2(packh2(v.x, v.y), packh2(v.z, v.w));
        }
    }
    __syncthreads();

    float acc[4][4][4];
#pragma unroll
    for (int m = 0; m < 4; m++)
#pragma unroll
        for (int nt = 0; nt < 4; nt++)
#pragma unroll
            for (int i = 0; i < 4; i++) acc[m][nt][i] = 0.f;

#pragma unroll
    for (int ks = 0; ks < 8; ks++) {
        uint32_t a[4][4];
#pragma unroll
        for (int m = 0; m < 4; m++)
            ldsm_x4(xs_sm + ((m * 16 + (lane & 15)) * PSTR + ks * 16 + (lane >> 4) * 8) * 2,
                    a[m][0], a[m][1], a[m][2], a[m][3]);
        uint32_t kfb[4][2];
#pragma unroll
        for (int p = 0; p < 2; p++) {
            uint32_t r0, r1, r2, r3;
            ldsm_x4(ws_sm + ((n0 + p * 16 + ((mi & 2) ? 8 : 0) + lr) * PSTR
                             + ks * 16 + (mi & 1) * 8) * 2, r0, r1, r2, r3);
            kfb[2*p][0]   = r0; kfb[2*p][1]   = r1;
            kfb[2*p+1][0] = r2; kfb[2*p+1][1] = r3;
        }
#pragma unroll
        for (int nt = 0; nt < 4; nt++)
#pragma unroll
            for (int m = 0; m < 4; m++)
                hmma(acc[m][nt], a[m], kfb[nt], acc[m][nt]);
    }

#pragma unroll
    for (int m = 0; m < 4; m++) {
        const int row = m0 + m * 16 + gr;
#pragma unroll
        for (int nt = 0; nt < 4; nt++) {
            const int col = n0 + nt * 8 + 2 * tig;
            const float b0 = bp[col], b1 = bp[col + 1];
            *(float2*)(out + (size_t)row * CC + col) =
                make_float2(acc[m][nt][0] + b0, acc[m][nt][1] + b1);
            *(float2*)(out + (size_t)(row + 8) * CC + col) =
                make_float2(acc[m][nt][2] + b0, acc[m][nt][3] + b1);
        }
    }
}

// ---------------------------------------------------------------------------
extern "C" void kernel_launch(void* const* d_in, const int* in_sizes, int n_in,
                              void* d_out, int out_size)
{
    const float* x  = (const float*)d_in[0];
    const float* Wk = (const float*)d_in[1];
    const float* Wq = (const float*)d_in[2];
    const float* Wv = (const float*)d_in[3];
    const float* Wp = (const float*)d_in[4];
    const float* bp = (const float*)d_in[5];
    float* out = (float*)d_out;

    static bool attr_done = false;
    if (!attr_done) {
        cudaFuncSetAttribute(qkv_hmma_kernel,
                             cudaFuncAttributeMaxDynamicSharedMemorySize, PROJ_SMEM);
        cudaFuncSetAttribute(proj_hmma_kernel,
                             cudaFuncAttributeMaxDynamicSharedMemorySize, PROJ_SMEM);
        attr_done = true;
    }

    qkv_hmma_kernel<<<dim3(NROWS / PROWS, 3), 128, PROJ_SMEM>>>(x, Wk, Wq, Wv);
    attn_mma_kernel<<<dim3(NSEGMAX, QTILES, HH * BB), 256>>>();
    combine_kernel<<<NROWS * HH / 128, 128>>>();
    proj_hmma_kernel<<<NROWS / PROWS, 128, PROJ_SMEM>>>(Wp, bp, out);
}